// round 4
// baseline (speedup 1.0000x reference)
#include <cuda_runtime.h>

#define MROWS 20000
#define DCH   128
#define FFH   512

// ---------------- scratch (static device globals; no allocation) ----------------
__device__ float g_h   [MROWS*DCH];   // current layer input
__device__ float g_vall[MROWS*DCH];   // per-head V projections (heads concat on cols)
__device__ float g_y0  [MROWS*DCH];   // h + gat_out (pre-BN1)
__device__ float g_z   [MROWS*DCH];   // BN1 output
__device__ float g_ff1 [MROWS*FFH];   // relu(z@W1+b1)
__device__ float g_y1  [MROWS*DCH];   // z + ff (pre-BN2)
__device__ float g_wvcat[3*DCH*DCH];  // Wv repacked [l][d][g*16+k]
__device__ float g_part [256*DCH];    // per-block partial col sums
__device__ float g_part2[256*DCH];    // per-block partial col sumsq
__device__ float g_scale[DCH];
__device__ float g_shift[DCH];
__device__ unsigned char g_mask[MROWS];

// ---------------- small prep kernels ----------------
__global__ void k_copy_in(const float4* __restrict__ x) {
    int i = blockIdx.x * blockDim.x + threadIdx.x;   // 640000 float4 exactly
    ((float4*)g_h)[i] = x[i];
}

__global__ void k_prep_wv(const float* __restrict__ Wv) {
    int idx = blockIdx.x * blockDim.x + threadIdx.x;
    if (idx < 3*DCH*DCH) {
        int l = idx / (DCH*DCH);
        int r = idx % (DCH*DCH);
        int d = r / DCH;
        int col = r % DCH;
        int g = col >> 4, k = col & 15;
        // Wv: (L,H,D,KD)
        g_wvcat[idx] = Wv[((l*8 + g)*DCH + d)*16 + k];
    }
}

__global__ void k_zero_mask() {
    int i = blockIdx.x * blockDim.x + threadIdx.x;
    if (i < MROWS) g_mask[i] = 0;
}

__global__ void k_scatter_mask(const int* __restrict__ ei, int E) {
    int e = blockIdx.x * blockDim.x + threadIdx.x;
    if (e < E) g_mask[ei[E + e]] = 1;   // dst = edge_index[1]
}

// ---------------- GEMM 1: Vall = h @ wvcat[l]   (M=20000, K=128, N=128) ----------------
__global__ __launch_bounds__(256) void k_gemm_v(int l) {
    const float* __restrict__ B = g_wvcat + l*DCH*DCH;
    __shared__ float As[16][132];
    __shared__ float Bs[16][128];
    int tid = threadIdx.x;
    int tx = tid & 15, ty = tid >> 4;
    int row0 = blockIdx.x * 128;
    float acc[8][8];
    #pragma unroll
    for (int i = 0; i < 8; i++)
        #pragma unroll
        for (int j = 0; j < 8; j++) acc[i][j] = 0.f;

    for (int k0 = 0; k0 < 128; k0 += 16) {
        #pragma unroll
        for (int t = 0; t < 2; t++) {
            int j = tid + t*256;
            int r = j >> 2, cg = (j & 3) << 2;
            float4 v = make_float4(0.f,0.f,0.f,0.f);
            int gr = row0 + r;
            if (gr < MROWS) v = *(const float4*)(g_h + gr*128 + k0 + cg);
            As[cg+0][r] = v.x; As[cg+1][r] = v.y; As[cg+2][r] = v.z; As[cg+3][r] = v.w;
        }
        #pragma unroll
        for (int t = 0; t < 2; t++) {
            int j = tid + t*256;
            int r = j >> 5, c = (j & 31) << 2;
            *(float4*)(&Bs[r][c]) = *(const float4*)(B + (k0 + r)*128 + c);
        }
        __syncthreads();
        #pragma unroll
        for (int k = 0; k < 16; k++) {
            float a[8], b[8];
            *(float4*)&a[0] = *(const float4*)&As[k][ty*8];
            *(float4*)&a[4] = *(const float4*)&As[k][ty*8+4];
            *(float4*)&b[0] = *(const float4*)&Bs[k][tx*8];
            *(float4*)&b[4] = *(const float4*)&Bs[k][tx*8+4];
            #pragma unroll
            for (int i = 0; i < 8; i++)
                #pragma unroll
                for (int j2 = 0; j2 < 8; j2++)
                    acc[i][j2] += a[i] * b[j2];
        }
        __syncthreads();
    }
    #pragma unroll
    for (int i = 0; i < 8; i++) {
        int gr = row0 + ty*8 + i;
        if (gr < MROWS) {
            #pragma unroll
            for (int j2 = 0; j2 < 8; j2 += 4) {
                float4 v = make_float4(acc[i][j2], acc[i][j2+1], acc[i][j2+2], acc[i][j2+3]);
                *(float4*)(g_vall + gr*128 + tx*8 + j2) = v;
            }
        }
    }
}

// ---------------- GEMM 2: GAT out + residual + BN1 partial stats ----------------
// Per g (blockIdx.z): out[g*2500+m, :] = mask * (Avw @ Wout_flat) where
// Avw[m, h2*16+k] = Vall[8m+h2, g*16+k]. y0 = h + out.
__global__ __launch_bounds__(256) void k_gemm_gat(const float* __restrict__ Bw) {
    __shared__ float As[16][132];
    __shared__ float Bs[16][128];
    int tid = threadIdx.x;
    int tx = tid & 15, ty = tid >> 4;
    int g  = blockIdx.z;
    int m0 = blockIdx.x * 128;
    float acc[8][8];
    #pragma unroll
    for (int i = 0; i < 8; i++)
        #pragma unroll
        for (int j = 0; j < 8; j++) acc[i][j] = 0.f;

    for (int k0 = 0; k0 < 128; k0 += 16) {
        int h2 = k0 >> 4;
        #pragma unroll
        for (int t = 0; t < 2; t++) {
            int j = tid + t*256;
            int r = j >> 2, cg = (j & 3) << 2;
            float4 v = make_float4(0.f,0.f,0.f,0.f);
            int gm = m0 + r;
            if (gm < 2500) v = *(const float4*)(g_vall + (8*gm + h2)*128 + g*16 + cg);
            As[cg+0][r] = v.x; As[cg+1][r] = v.y; As[cg+2][r] = v.z; As[cg+3][r] = v.w;
        }
        #pragma unroll
        for (int t = 0; t < 2; t++) {
            int j = tid + t*256;
            int r = j >> 5, c = (j & 31) << 2;
            *(float4*)(&Bs[r][c]) = *(const float4*)(Bw + (k0 + r)*128 + c);
        }
        __syncthreads();
        #pragma unroll
        for (int k = 0; k < 16; k++) {
            float a[8], b[8];
            *(float4*)&a[0] = *(const float4*)&As[k][ty*8];
            *(float4*)&a[4] = *(const float4*)&As[k][ty*8+4];
            *(float4*)&b[0] = *(const float4*)&Bs[k][tx*8];
            *(float4*)&b[4] = *(const float4*)&Bs[k][tx*8+4];
            #pragma unroll
            for (int i = 0; i < 8; i++)
                #pragma unroll
                for (int j2 = 0; j2 < 8; j2++)
                    acc[i][j2] += a[i] * b[j2];
        }
        __syncthreads();
    }

    // epilogue: y0 = h + mask*out, plus per-column partial sums for BN1 stats
    float colsum[8], colsq[8];
    #pragma unroll
    for (int j2 = 0; j2 < 8; j2++) { colsum[j2] = 0.f; colsq[j2] = 0.f; }
    #pragma unroll
    for (int i = 0; i < 8; i++) {
        int gm = m0 + ty*8 + i;
        if (gm < 2500) {
            int n2 = g*2500 + gm;
            float mk = g_mask[n2] ? 1.f : 0.f;
            #pragma unroll
            for (int q = 0; q < 2; q++) {
                float4 hv = *(const float4*)(g_h + n2*128 + tx*8 + q*4);
                float4 v;
                v.x = hv.x + mk*acc[i][q*4+0];
                v.y = hv.y + mk*acc[i][q*4+1];
                v.z = hv.z + mk*acc[i][q*4+2];
                v.w = hv.w + mk*acc[i][q*4+3];
                *(float4*)(g_y0 + n2*128 + tx*8 + q*4) = v;
                colsum[q*4+0] += v.x; colsq[q*4+0] += v.x*v.x;
                colsum[q*4+1] += v.y; colsq[q*4+1] += v.y*v.y;
                colsum[q*4+2] += v.z; colsq[q*4+2] += v.z*v.z;
                colsum[q*4+3] += v.w; colsq[q*4+3] += v.w*v.w;
            }
        }
    }
    float* redS = &As[0][0];   // 2112 floats >= 2048
    float* redQ = &Bs[0][0];   // 2048 floats
    #pragma unroll
    for (int j2 = 0; j2 < 8; j2++) {
        redS[ty*128 + tx*8 + j2] = colsum[j2];
        redQ[ty*128 + tx*8 + j2] = colsq[j2];
    }
    __syncthreads();
    if (tid < 128) {
        float s = 0.f, q = 0.f;
        #pragma unroll
        for (int t = 0; t < 16; t++) { s += redS[t*128 + tid]; q += redQ[t*128 + tid]; }
        int slot = g*gridDim.x + blockIdx.x;
        g_part [slot*128 + tid] = s;
        g_part2[slot*128 + tid] = q;
    }
}

// ---------------- GEMM 3: ff1 = relu(z @ W1 + b1)   (M=20000, K=128, N=512) ----------------
__global__ __launch_bounds__(256) void k_gemm_ff1(const float* __restrict__ B,
                                                  const float* __restrict__ bias) {
    __shared__ float As[16][132];
    __shared__ float Bs[16][128];
    int tid = threadIdx.x;
    int tx = tid & 15, ty = tid >> 4;
    int row0 = blockIdx.x * 128;
    int col0 = blockIdx.y * 128;
    float acc[8][8];
    #pragma unroll
    for (int i = 0; i < 8; i++)
        #pragma unroll
        for (int j = 0; j < 8; j++) acc[i][j] = 0.f;

    for (int k0 = 0; k0 < 128; k0 += 16) {
        #pragma unroll
        for (int t = 0; t < 2; t++) {
            int j = tid + t*256;
            int r = j >> 2, cg = (j & 3) << 2;
            float4 v = make_float4(0.f,0.f,0.f,0.f);
            int gr = row0 + r;
            if (gr < MROWS) v = *(const float4*)(g_z + gr*128 + k0 + cg);
            As[cg+0][r] = v.x; As[cg+1][r] = v.y; As[cg+2][r] = v.z; As[cg+3][r] = v.w;
        }
        #pragma unroll
        for (int t = 0; t < 2; t++) {
            int j = tid + t*256;
            int r = j >> 5, c = (j & 31) << 2;
            *(float4*)(&Bs[r][c]) = *(const float4*)(B + (k0 + r)*512 + col0 + c);
        }
        __syncthreads();
        #pragma unroll
        for (int k = 0; k < 16; k++) {
            float a[8], b[8];
            *(float4*)&a[0] = *(const float4*)&As[k][ty*8];
            *(float4*)&a[4] = *(const float4*)&As[k][ty*8+4];
            *(float4*)&b[0] = *(const float4*)&Bs[k][tx*8];
            *(float4*)&b[4] = *(const float4*)&Bs[k][tx*8+4];
            #pragma unroll
            for (int i = 0; i < 8; i++)
                #pragma unroll
                for (int j2 = 0; j2 < 8; j2++)
                    acc[i][j2] += a[i] * b[j2];
        }
        __syncthreads();
    }
    float bb[8];
    #pragma unroll
    for (int j2 = 0; j2 < 8; j2++) bb[j2] = bias[col0 + tx*8 + j2];
    #pragma unroll
    for (int i = 0; i < 8; i++) {
        int gr = row0 + ty*8 + i;
        if (gr < MROWS) {
            #pragma unroll
            for (int q = 0; q < 2; q++) {
                float4 v;
                v.x = fmaxf(acc[i][q*4+0] + bb[q*4+0], 0.f);
                v.y = fmaxf(acc[i][q*4+1] + bb[q*4+1], 0.f);
                v.z = fmaxf(acc[i][q*4+2] + bb[q*4+2], 0.f);
                v.w = fmaxf(acc[i][q*4+3] + bb[q*4+3], 0.f);
                *(float4*)(g_ff1 + gr*512 + col0 + tx*8 + q*4) = v;
            }
        }
    }
}

// ---------------- GEMM 4: y1 = z + ff1 @ W2 + b2, BN2 partial stats  (K=512, N=128) ----------------
__global__ __launch_bounds__(256) void k_gemm_ff2(const float* __restrict__ B,
                                                  const float* __restrict__ bias) {
    __shared__ float As[16][132];
    __shared__ float Bs[16][128];
    int tid = threadIdx.x;
    int tx = tid & 15, ty = tid >> 4;
    int row0 = blockIdx.x * 128;
    float acc[8][8];
    #pragma unroll
    for (int i = 0; i < 8; i++)
        #pragma unroll
        for (int j = 0; j < 8; j++) acc[i][j] = 0.f;

    for (int k0 = 0; k0 < 512; k0 += 16) {
        #pragma unroll
        for (int t = 0; t < 2; t++) {
            int j = tid + t*256;
            int r = j >> 2, cg = (j & 3) << 2;
            float4 v = make_float4(0.f,0.f,0.f,0.f);
            int gr = row0 + r;
            if (gr < MROWS) v = *(const float4*)(g_ff1 + gr*512 + k0 + cg);
            As[cg+0][r] = v.x; As[cg+1][r] = v.y; As[cg+2][r] = v.z; As[cg+3][r] = v.w;
        }
        #pragma unroll
        for (int t = 0; t < 2; t++) {
            int j = tid + t*256;
            int r = j >> 5, c = (j & 31) << 2;
            *(float4*)(&Bs[r][c]) = *(const float4*)(B + (k0 + r)*128 + c);
        }
        __syncthreads();
        #pragma unroll
        for (int k = 0; k < 16; k++) {
            float a[8], b[8];
            *(float4*)&a[0] = *(const float4*)&As[k][ty*8];
            *(float4*)&a[4] = *(const float4*)&As[k][ty*8+4];
            *(float4*)&b[0] = *(const float4*)&Bs[k][tx*8];
            *(float4*)&b[4] = *(const float4*)&Bs[k][tx*8+4];
            #pragma unroll
            for (int i = 0; i < 8; i++)
                #pragma unroll
                for (int j2 = 0; j2 < 8; j2++)
                    acc[i][j2] += a[i] * b[j2];
        }
        __syncthreads();
    }

    float bb[8];
    #pragma unroll
    for (int j2 = 0; j2 < 8; j2++) bb[j2] = bias[tx*8 + j2];
    float colsum[8], colsq[8];
    #pragma unroll
    for (int j2 = 0; j2 < 8; j2++) { colsum[j2] = 0.f; colsq[j2] = 0.f; }
    #pragma unroll
    for (int i = 0; i < 8; i++) {
        int gr = row0 + ty*8 + i;
        if (gr < MROWS) {
            #pragma unroll
            for (int q = 0; q < 2; q++) {
                float4 zv = *(const float4*)(g_z + gr*128 + tx*8 + q*4);
                float4 v;
                v.x = zv.x + acc[i][q*4+0] + bb[q*4+0];
                v.y = zv.y + acc[i][q*4+1] + bb[q*4+1];
                v.z = zv.z + acc[i][q*4+2] + bb[q*4+2];
                v.w = zv.w + acc[i][q*4+3] + bb[q*4+3];
                *(float4*)(g_y1 + gr*128 + tx*8 + q*4) = v;
                colsum[q*4+0] += v.x; colsq[q*4+0] += v.x*v.x;
                colsum[q*4+1] += v.y; colsq[q*4+1] += v.y*v.y;
                colsum[q*4+2] += v.z; colsq[q*4+2] += v.z*v.z;
                colsum[q*4+3] += v.w; colsq[q*4+3] += v.w*v.w;
            }
        }
    }
    float* redS = &As[0][0];
    float* redQ = &Bs[0][0];
    #pragma unroll
    for (int j2 = 0; j2 < 8; j2++) {
        redS[ty*128 + tx*8 + j2] = colsum[j2];
        redQ[ty*128 + tx*8 + j2] = colsq[j2];
    }
    __syncthreads();
    if (tid < 128) {
        float s = 0.f, q = 0.f;
        #pragma unroll
        for (int t = 0; t < 16; t++) { s += redS[t*128 + tid]; q += redQ[t*128 + tid]; }
        int slot = blockIdx.x;
        g_part [slot*128 + tid] = s;
        g_part2[slot*128 + tid] = q;
    }
}

// ---------------- BN stats finalize (deterministic) ----------------
__global__ void k_finalize(int nslots, const float* __restrict__ w, const float* __restrict__ b) {
    int c = threadIdx.x;   // 128
    float s = 0.f, q = 0.f;
    for (int i = 0; i < nslots; i++) { s += g_part[i*128 + c]; q += g_part2[i*128 + c]; }
    float inv = 1.f / (float)MROWS;
    float mu = s * inv;
    float var = q * inv - mu*mu;
    float rstd = rsqrtf(var + 1e-5f);
    float sc = rstd * w[c];
    g_scale[c] = sc;
    g_shift[c] = b[c] - mu * sc;
}

// ---------------- BN apply ----------------
// which==0: g_y0 -> g_z ;  which==1: g_y1 -> g_h (or extdst if given)
__global__ void k_bn(int which, float* __restrict__ extdst) {
    int i = blockIdx.x * blockDim.x + threadIdx.x;   // 640000 float4 exactly
    const float4* src = (const float4*)(which == 0 ? (const float*)g_y0 : (const float*)g_y1);
    float4* dst = extdst ? (float4*)extdst
                         : (float4*)(which == 0 ? (float*)g_z : (float*)g_h);
    float4 v = src[i];
    int c = (i & 31) << 2;
    v.x = v.x * g_scale[c+0] + g_shift[c+0];
    v.y = v.y * g_scale[c+1] + g_shift[c+1];
    v.z = v.z * g_scale[c+2] + g_shift[c+2];
    v.w = v.w * g_scale[c+3] + g_shift[c+3];
    dst[i] = v;
}

// ---------------- launch ----------------
extern "C" void kernel_launch(void* const* d_in, const int* in_sizes, int n_in,
                              void* d_out, int out_size) {
    const float* x    = (const float*)d_in[0];
    const int*   ei   = (const int*)  d_in[1];
    const float* Wv   = (const float*)d_in[4];
    const float* Wout = (const float*)d_in[5];
    const float* bn1w = (const float*)d_in[6];
    const float* bn1b = (const float*)d_in[7];
    const float* W1   = (const float*)d_in[8];
    const float* b1   = (const float*)d_in[9];
    const float* W2   = (const float*)d_in[10];
    const float* b2   = (const float*)d_in[11];
    const float* bn2w = (const float*)d_in[12];
    const float* bn2b = (const float*)d_in[13];
    float* out = (float*)d_out;
    int E = in_sizes[1] / 2;

    k_copy_in<<<2500, 256>>>((const float4*)x);
    k_prep_wv<<<(3*DCH*DCH + 255)/256, 256>>>(Wv);
    k_zero_mask<<<(MROWS + 255)/256, 256>>>();
    k_scatter_mask<<<(E + 255)/256, 256>>>(ei, E);

    for (int l = 0; l < 3; l++) {
        k_gemm_v<<<157, 256>>>(l);
        dim3 gg(20, 1, 8);
        k_gemm_gat<<<gg, 256>>>(Wout + l*8*16*128);
        k_finalize<<<1, 128>>>(160, bn1w + l*128, bn1b + l*128);
        k_bn<<<2500, 256>>>(0, nullptr);
        dim3 gf(157, 4);
        k_gemm_ff1<<<gf, 256>>>(W1 + l*128*512, b1 + l*512);
        k_gemm_ff2<<<157, 256>>>(W2 + l*512*128, b2 + l*128);
        k_finalize<<<1, 128>>>(157, bn2w + l*128, bn2b + l*128);
        k_bn<<<2500, 256>>>(1, (l == 2) ? out : nullptr);
    }
}

// round 5
// speedup vs baseline: 1.7989x; 1.7989x over previous
#include <cuda_runtime.h>
#include <cuda_bf16.h>

#define MROWS 20000
#define DCH   128
#define FFH   512
#define BM    128
#define BK    32

// ---------------- scratch (static device globals; no allocation) ----------------
__device__ __nv_bfloat16 g_wv_hi[3*DCH*DCH], g_wv_lo[3*DCH*DCH];
__device__ __nv_bfloat16 g_wo_hi[3*DCH*DCH], g_wo_lo[3*DCH*DCH];
__device__ __nv_bfloat16 g_w1_hi[3*DCH*FFH], g_w1_lo[3*DCH*FFH];
__device__ __nv_bfloat16 g_w2_hi[3*FFH*DCH], g_w2_lo[3*FFH*DCH];
__device__ __nv_bfloat16 g_P_hi[MROWS*DCH],  g_P_lo[MROWS*DCH];   // permuted V (gat A)
__device__ __nv_bfloat16 g_z_hi[MROWS*DCH],  g_z_lo[MROWS*DCH];   // BN1(y0) split (ff1 A)
__device__ __nv_bfloat16 g_f_hi[MROWS*FFH],  g_f_lo[MROWS*FFH];   // relu ff1 split (ff2 A)
__device__ float g_y0[MROWS*DCH];     // h + gat (pre-BN1), fp32 for residual
__device__ float g_y1[MROWS*DCH];     // z + ff  (pre-BN2), fp32
__device__ float g_part [157*DCH], g_part2[157*DCH];
__device__ float g_scale1[DCH], g_shift1[DCH], g_scale2[DCH], g_shift2[DCH];
__device__ unsigned char g_mask[MROWS];

// ---------------- helpers ----------------
__device__ __forceinline__ unsigned sptr(const void* p){
    return (unsigned)__cvta_generic_to_shared(p);
}
__device__ __forceinline__ void split2(float a, float b, unsigned& hi, unsigned& lo){
    __nv_bfloat16 ha = __float2bfloat16(a), hb = __float2bfloat16(b);
    float ra = a - __bfloat162float(ha);
    float rb = b - __bfloat162float(hb);
    __nv_bfloat162 H; H.x = ha; H.y = hb;
    __nv_bfloat162 L = __floats2bfloat162_rn(ra, rb);
    hi = *reinterpret_cast<unsigned*>(&H);
    lo = *reinterpret_cast<unsigned*>(&L);
}
__device__ __forceinline__ void ldsm4(unsigned r[4], unsigned a){
    asm volatile("ldmatrix.sync.aligned.m8n8.x4.shared.b16 {%0,%1,%2,%3}, [%4];"
        : "=r"(r[0]), "=r"(r[1]), "=r"(r[2]), "=r"(r[3]) : "r"(a));
}
__device__ __forceinline__ void ldsm4t(unsigned r[4], unsigned a){
    asm volatile("ldmatrix.sync.aligned.m8n8.x4.trans.shared.b16 {%0,%1,%2,%3}, [%4];"
        : "=r"(r[0]), "=r"(r[1]), "=r"(r[2]), "=r"(r[3]) : "r"(a));
}
__device__ __forceinline__ void mma_b(float c[4], const unsigned a[4], const unsigned b[2]){
    asm volatile("mma.sync.aligned.m16n8k16.row.col.f32.bf16.bf16.f32 "
        "{%0,%1,%2,%3}, {%4,%5,%6,%7}, {%8,%9}, {%0,%1,%2,%3};"
        : "+f"(c[0]), "+f"(c[1]), "+f"(c[2]), "+f"(c[3])
        : "r"(a[0]), "r"(a[1]), "r"(a[2]), "r"(a[3]), "r"(b[0]), "r"(b[1]));
}

// A smem: 128 rows x 32 halves, stride 40 halves (80B, conflict-free ldmatrix)
// B smem:  32 rows x 128 halves, stride 136 halves (272B)
#define ASTR 40
#define BSTR 136

// ---------------- tile loaders (256 threads) ----------------
__device__ __forceinline__ void load_A_f32(
    __nv_bfloat16* sAh, __nv_bfloat16* sAl,
    const float* __restrict__ src, int row0, int k0,
    const float* __restrict__ scale, const float* __restrict__ shift)
{
    int tid = threadIdx.x;
    #pragma unroll
    for (int i = 0; i < 4; i++){
        int j = tid + i*256;
        int r = j >> 3, c4 = (j & 7) << 2;
        int gr = row0 + r;
        float4 v = make_float4(0.f,0.f,0.f,0.f);
        if (gr < MROWS) v = *(const float4*)(src + (size_t)gr*DCH + k0 + c4);
        if (scale){
            int c = k0 + c4;
            v.x = fmaf(v.x, scale[c+0], shift[c+0]);
            v.y = fmaf(v.y, scale[c+1], shift[c+1]);
            v.z = fmaf(v.z, scale[c+2], shift[c+2]);
            v.w = fmaf(v.w, scale[c+3], shift[c+3]);
        }
        unsigned h0,l0,h1,l1;
        split2(v.x, v.y, h0, l0);
        split2(v.z, v.w, h1, l1);
        *(uint2*)(sAh + r*ASTR + c4) = make_uint2(h0, h1);
        *(uint2*)(sAl + r*ASTR + c4) = make_uint2(l0, l1);
    }
}

__device__ __forceinline__ void load_A_bf16(
    __nv_bfloat16* sAh, __nv_bfloat16* sAl,
    const __nv_bfloat16* __restrict__ Ah, const __nv_bfloat16* __restrict__ Al,
    int lda, int row0, int k0)
{
    int tid = threadIdx.x;
    #pragma unroll
    for (int i = 0; i < 2; i++){
        int j = tid + i*256;              // 512 uint4 total (128 rows x 4)
        int r = j >> 2, c8 = (j & 3) << 3;
        int gr = row0 + r;
        uint4 vh = make_uint4(0,0,0,0), vl = make_uint4(0,0,0,0);
        if (gr < MROWS){
            vh = *(const uint4*)(Ah + (size_t)gr*lda + k0 + c8);
            vl = *(const uint4*)(Al + (size_t)gr*lda + k0 + c8);
        }
        *(uint4*)(sAh + r*ASTR + c8) = vh;
        *(uint4*)(sAl + r*ASTR + c8) = vl;
    }
}

__device__ __forceinline__ void load_B_bf16(
    __nv_bfloat16* sBh, __nv_bfloat16* sBl,
    const __nv_bfloat16* __restrict__ Bh, const __nv_bfloat16* __restrict__ Bl,
    int ldb, int k0, int col0)
{
    int tid = threadIdx.x;
    #pragma unroll
    for (int i = 0; i < 2; i++){
        int j = tid + i*256;              // 512 uint4 total (32 rows x 16)
        int r = j >> 4, c8 = (j & 15) << 3;
        size_t off = (size_t)(k0 + r)*ldb + col0 + c8;
        *(uint4*)(sBh + r*BSTR + c8) = *(const uint4*)(Bh + off);
        *(uint4*)(sBl + r*BSTR + c8) = *(const uint4*)(Bl + off);
    }
}

// ---------------- compute: one 128x128x32 stage, 3-pass split ----------------
__device__ __forceinline__ void compute_stage(
    unsigned saH, unsigned saL, unsigned sbH, unsigned sbL, float acc[2][8][4])
{
    int lane = threadIdx.x & 31;
    int warp = threadIdx.x >> 5;
    int wm = warp >> 1, wn = warp & 1;
    #pragma unroll
    for (int ks = 0; ks < 2; ks++){
        unsigned aH[2][4], aL[2][4], bH[8][2], bL[8][2];
        #pragma unroll
        for (int mt = 0; mt < 2; mt++){
            unsigned off = (unsigned)((wm*32 + mt*16 + (lane & 15))*(ASTR*2) + ks*32 + ((lane >> 4) << 4));
            ldsm4(aH[mt], saH + off);
            ldsm4(aL[mt], saL + off);
        }
        #pragma unroll
        for (int p = 0; p < 4; p++){
            int kk = ks*16 + (lane & 15);
            int n  = wn*64 + p*16 + ((lane & 16) ? 8 : 0);
            unsigned off = (unsigned)(kk*(BSTR*2) + n*2);
            unsigned t[4];
            ldsm4t(t, sbH + off);
            bH[2*p][0]=t[0]; bH[2*p][1]=t[1]; bH[2*p+1][0]=t[2]; bH[2*p+1][1]=t[3];
            ldsm4t(t, sbL + off);
            bL[2*p][0]=t[0]; bL[2*p][1]=t[1]; bL[2*p+1][0]=t[2]; bL[2*p+1][1]=t[3];
        }
        #pragma unroll
        for (int mt = 0; mt < 2; mt++)
            #pragma unroll
            for (int nt = 0; nt < 8; nt++){
                mma_b(acc[mt][nt], aH[mt], bH[nt]);
                mma_b(acc[mt][nt], aH[mt], bL[nt]);
                mma_b(acc[mt][nt], aL[mt], bH[nt]);
            }
    }
}

// deterministic per-block column sum/sumsq from final acc values
__device__ __forceinline__ void block_stats(float acc[2][8][4], float* redS, float* redQ, int slot)
{
    int tid = threadIdx.x;
    int lane = tid & 31, warp = tid >> 5, wm = warp >> 1, wn = warp & 1;
    #pragma unroll
    for (int nt = 0; nt < 8; nt++){
        float se=0.f, so=0.f, qe=0.f, qo=0.f;
        #pragma unroll
        for (int mt = 0; mt < 2; mt++){
            float a0=acc[mt][nt][0], a1=acc[mt][nt][1], a2=acc[mt][nt][2], a3=acc[mt][nt][3];
            se += a0 + a2; so += a1 + a3;
            qe += a0*a0 + a2*a2; qo += a1*a1 + a3*a3;
        }
        #pragma unroll
        for (int off = 16; off >= 4; off >>= 1){
            se += __shfl_down_sync(0xffffffffu, se, off);
            so += __shfl_down_sync(0xffffffffu, so, off);
            qe += __shfl_down_sync(0xffffffffu, qe, off);
            qo += __shfl_down_sync(0xffffffffu, qo, off);
        }
        if (lane < 4){
            int c = wn*64 + nt*8 + lane*2;
            redS[wm*128 + c] = se; redS[wm*128 + c + 1] = so;
            redQ[wm*128 + c] = qe; redQ[wm*128 + c + 1] = qo;
        }
    }
    __syncthreads();
    if (tid < 128){
        float s = redS[tid] + redS[128+tid] + redS[256+tid] + redS[384+tid];
        float q = redQ[tid] + redQ[128+tid] + redQ[256+tid] + redQ[384+tid];
        g_part [slot*128 + tid] = s;
        g_part2[slot*128 + tid] = q;
    }
}

#define ACC_INIT float acc[2][8][4]; \
    _Pragma("unroll") for (int _i=0;_i<2;_i++) \
    _Pragma("unroll") for (int _j=0;_j<8;_j++) \
    _Pragma("unroll") for (int _k=0;_k<4;_k++) acc[_i][_j][_k]=0.f;

#define EPI_COORDS int tid = threadIdx.x; int lane = tid & 31; int warp = tid >> 5; \
    int wm = warp >> 1, wn = warp & 1; \
    int rb = row0 + wm*32 + (lane>>2); \
    int cb = wn*64 + ((lane&3)<<1); (void)cb;

// ---------------- GEMM 1: P(permuted,split) = [x | BN2(y1)] @ Wv ----------------
__global__ __launch_bounds__(256) void k_gemm_v(const float* __restrict__ srcExt, int l)
{
    __shared__ __align__(16) __nv_bfloat16 sAh[128*ASTR], sAl[128*ASTR], sBh[32*BSTR], sBl[32*BSTR];
    ACC_INIT
    const float* src   = srcExt ? srcExt : g_y1;
    const float* scale = srcExt ? (const float*)nullptr : g_scale2;
    const float* shift = srcExt ? (const float*)nullptr : g_shift2;
    const __nv_bfloat16* Bh = g_wv_hi + l*DCH*DCH;
    const __nv_bfloat16* Bl = g_wv_lo + l*DCH*DCH;
    int row0 = blockIdx.x*BM;
    unsigned saH = sptr(sAh), saL = sptr(sAl), sbH = sptr(sBh), sbL = sptr(sBl);
    for (int k0 = 0; k0 < DCH; k0 += BK){
        load_A_f32(sAh, sAl, src, row0, k0, scale, shift);
        load_B_bf16(sBh, sBl, Bh, Bl, DCH, k0, 0);
        __syncthreads();
        compute_stage(saH, saL, sbH, sbL, acc);
        __syncthreads();
    }
    EPI_COORDS
    #pragma unroll
    for (int mt = 0; mt < 2; mt++)
    #pragma unroll
    for (int hf = 0; hf < 2; hf++){
        int r = rb + mt*16 + hf*8;
        if (r < MROWS){
            int m = r >> 3, rr = r & 7;
            #pragma unroll
            for (int nt = 0; nt < 8; nt++){
                int c = cb + nt*8;
                int g = c >> 4;
                size_t off = (size_t)(g*2500 + m)*DCH + (rr<<4) + (c & 15);
                unsigned hi, lo;
                split2(acc[mt][nt][hf*2], acc[mt][nt][hf*2+1], hi, lo);
                *(unsigned*)(g_P_hi + off) = hi;
                *(unsigned*)(g_P_lo + off) = lo;
            }
        }
    }
}

// ---------------- GEMM 2: y0 = resid + mask*(P @ Wout), BN1 partial stats ----------------
__global__ __launch_bounds__(256) void k_gemm_gat(int l, const float* __restrict__ residExt)
{
    __shared__ __align__(16) __nv_bfloat16 sAh[128*ASTR], sAl[128*ASTR], sBh[32*BSTR], sBl[32*BSTR];
    ACC_INIT
    const __nv_bfloat16* Bh = g_wo_hi + l*DCH*DCH;
    const __nv_bfloat16* Bl = g_wo_lo + l*DCH*DCH;
    int row0 = blockIdx.x*BM;
    unsigned saH = sptr(sAh), saL = sptr(sAl), sbH = sptr(sBh), sbL = sptr(sBl);
    for (int k0 = 0; k0 < DCH; k0 += BK){
        load_A_bf16(sAh, sAl, g_P_hi, g_P_lo, DCH, row0, k0);
        load_B_bf16(sBh, sBl, Bh, Bl, DCH, k0, 0);
        __syncthreads();
        compute_stage(saH, saL, sbH, sbL, acc);
        __syncthreads();
    }
    EPI_COORDS
    const float* resid = residExt ? residExt : g_y1;
    bool bn = (residExt == nullptr);
    #pragma unroll
    for (int mt = 0; mt < 2; mt++)
    #pragma unroll
    for (int hf = 0; hf < 2; hf++){
        int r = rb + mt*16 + hf*8;
        if (r < MROWS){
            float mk = g_mask[r] ? 1.f : 0.f;
            #pragma unroll
            for (int nt = 0; nt < 8; nt++){
                int c = cb + nt*8;
                float2 hv = *(const float2*)(resid + (size_t)r*DCH + c);
                float h0 = hv.x, h1 = hv.y;
                if (bn){
                    h0 = fmaf(h0, g_scale2[c],   g_shift2[c]);
                    h1 = fmaf(h1, g_scale2[c+1], g_shift2[c+1]);
                }
                float v0 = fmaf(mk, acc[mt][nt][hf*2+0], h0);
                float v1 = fmaf(mk, acc[mt][nt][hf*2+1], h1);
                *(float2*)(g_y0 + (size_t)r*DCH + c) = make_float2(v0, v1);
                acc[mt][nt][hf*2+0] = v0; acc[mt][nt][hf*2+1] = v1;
            }
        } else {
            #pragma unroll
            for (int nt = 0; nt < 8; nt++){ acc[mt][nt][hf*2+0]=0.f; acc[mt][nt][hf*2+1]=0.f; }
        }
    }
    block_stats(acc, (float*)sAh, (float*)sBh, blockIdx.x);
}

// ---------------- GEMM 3: f = relu(z @ W1 + b1), bf16-split output ----------------
__global__ __launch_bounds__(256) void k_gemm_ff1(int l, const float* __restrict__ bias)
{
    __shared__ __align__(16) __nv_bfloat16 sAh[128*ASTR], sAl[128*ASTR], sBh[32*BSTR], sBl[32*BSTR];
    ACC_INIT
    const __nv_bfloat16* Bh = g_w1_hi + l*DCH*FFH;
    const __nv_bfloat16* Bl = g_w1_lo + l*DCH*FFH;
    int row0 = blockIdx.x*BM;
    int col0 = blockIdx.y*128;
    unsigned saH = sptr(sAh), saL = sptr(sAl), sbH = sptr(sBh), sbL = sptr(sBl);
    for (int k0 = 0; k0 < DCH; k0 += BK){
        load_A_bf16(sAh, sAl, g_z_hi, g_z_lo, DCH, row0, k0);
        load_B_bf16(sBh, sBl, Bh, Bl, FFH, k0, col0);
        __syncthreads();
        compute_stage(saH, saL, sbH, sbL, acc);
        __syncthreads();
    }
    EPI_COORDS
    #pragma unroll
    for (int mt = 0; mt < 2; mt++)
    #pragma unroll
    for (int hf = 0; hf < 2; hf++){
        int r = rb + mt*16 + hf*8;
        if (r < MROWS){
            #pragma unroll
            for (int nt = 0; nt < 8; nt++){
                int c = cb + nt*8;
                float v0 = fmaxf(acc[mt][nt][hf*2+0] + bias[col0+c],   0.f);
                float v1 = fmaxf(acc[mt][nt][hf*2+1] + bias[col0+c+1], 0.f);
                unsigned hi, lo;
                split2(v0, v1, hi, lo);
                size_t off = (size_t)r*FFH + col0 + c;
                *(unsigned*)(g_f_hi + off) = hi;
                *(unsigned*)(g_f_lo + off) = lo;
            }
        }
    }
}

// ---------------- GEMM 4: y1 = BN1(y0) + f @ W2 + b2, BN2 partial stats ----------------
__global__ __launch_bounds__(256) void k_gemm_ff2(int l, const float* __restrict__ bias)
{
    __shared__ __align__(16) __nv_bfloat16 sAh[128*ASTR], sAl[128*ASTR], sBh[32*BSTR], sBl[32*BSTR];
    ACC_INIT
    const __nv_bfloat16* Bh = g_w2_hi + l*FFH*DCH;
    const __nv_bfloat16* Bl = g_w2_lo + l*FFH*DCH;
    int row0 = blockIdx.x*BM;
    unsigned saH = sptr(sAh), saL = sptr(sAl), sbH = sptr(sBh), sbL = sptr(sBl);
    for (int k0 = 0; k0 < FFH; k0 += BK){
        load_A_bf16(sAh, sAl, g_f_hi, g_f_lo, FFH, row0, k0);
        load_B_bf16(sBh, sBl, Bh, Bl, DCH, k0, 0);
        __syncthreads();
        compute_stage(saH, saL, sbH, sbL, acc);
        __syncthreads();
    }
    EPI_COORDS
    #pragma unroll
    for (int mt = 0; mt < 2; mt++)
    #pragma unroll
    for (int hf = 0; hf < 2; hf++){
        int r = rb + mt*16 + hf*8;
        if (r < MROWS){
            #pragma unroll
            for (int nt = 0; nt < 8; nt++){
                int c = cb + nt*8;
                float2 yv = *(const float2*)(g_y0 + (size_t)r*DCH + c);
                float h0 = fmaf(yv.x, g_scale1[c],   g_shift1[c]);
                float h1 = fmaf(yv.y, g_scale1[c+1], g_shift1[c+1]);
                float v0 = h0 + acc[mt][nt][hf*2+0] + bias[c];
                float v1 = h1 + acc[mt][nt][hf*2+1] + bias[c+1];
                *(float2*)(g_y1 + (size_t)r*DCH + c) = make_float2(v0, v1);
                acc[mt][nt][hf*2+0] = v0; acc[mt][nt][hf*2+1] = v1;
            }
        } else {
            #pragma unroll
            for (int nt = 0; nt < 8; nt++){ acc[mt][nt][hf*2+0]=0.f; acc[mt][nt][hf*2+1]=0.f; }
        }
    }
    block_stats(acc, (float*)sAh, (float*)sBh, blockIdx.x);
}

// ---------------- small kernels ----------------
__global__ void k_prep_wv(const float* __restrict__ Wv){
    int idx = blockIdx.x*256 + threadIdx.x;
    if (idx < 3*DCH*DCH){
        int l = idx / (DCH*DCH);
        int rmd = idx % (DCH*DCH);
        int d = rmd / DCH, col = rmd % DCH;
        int g = col >> 4, k = col & 15;
        float v = Wv[((l*8 + g)*DCH + d)*16 + k];
        __nv_bfloat16 h = __float2bfloat16(v);
        g_wv_hi[idx] = h;
        g_wv_lo[idx] = __float2bfloat16(v - __bfloat162float(h));
    }
}

__global__ void k_prep_split(const float* __restrict__ src, int n, int which){
    int i = blockIdx.x*256 + threadIdx.x;
    if (i < n){
        float v = src[i];
        __nv_bfloat16 h = __float2bfloat16(v);
        __nv_bfloat16 lo = __float2bfloat16(v - __bfloat162float(h));
        if (which == 0){ g_wo_hi[i] = h; g_wo_lo[i] = lo; }
        else if (which == 1){ g_w1_hi[i] = h; g_w1_lo[i] = lo; }
        else { g_w2_hi[i] = h; g_w2_lo[i] = lo; }
    }
}

__global__ void k_zero_mask(){
    int i = blockIdx.x*256 + threadIdx.x;
    if (i < MROWS) g_mask[i] = 0;
}
__global__ void k_scatter_mask(const int* __restrict__ ei, int E){
    int e = blockIdx.x*256 + threadIdx.x;
    if (e < E) g_mask[ei[E + e]] = 1;   // dst row
}

__global__ void k_finalize(int nslots, const float* __restrict__ w,
                           const float* __restrict__ b, int which){
    int c = threadIdx.x;   // 128
    float s = 0.f, q = 0.f;
    for (int i = 0; i < nslots; i++){ s += g_part[i*128 + c]; q += g_part2[i*128 + c]; }
    float inv = 1.f / (float)MROWS;
    float mu = s * inv;
    float var = q * inv - mu*mu;
    float sc = rsqrtf(var + 1e-5f) * w[c];
    if (which == 1){ g_scale1[c] = sc; g_shift1[c] = b[c] - mu*sc; }
    else           { g_scale2[c] = sc; g_shift2[c] = b[c] - mu*sc; }
}

// BN1 apply + bf16 split: y0 -> z_hi/z_lo
__global__ void k_bnsplit(){
    int i = blockIdx.x*256 + threadIdx.x;     // 640000 float4 exactly
    float4 v = ((const float4*)g_y0)[i];
    int c = (i & 31) << 2;
    v.x = fmaf(v.x, g_scale1[c+0], g_shift1[c+0]);
    v.y = fmaf(v.y, g_scale1[c+1], g_shift1[c+1]);
    v.z = fmaf(v.z, g_scale1[c+2], g_shift1[c+2]);
    v.w = fmaf(v.w, g_scale1[c+3], g_shift1[c+3]);
    unsigned h0,l0,h1,l1;
    split2(v.x, v.y, h0, l0);
    split2(v.z, v.w, h1, l1);
    *(uint2*)(g_z_hi + (size_t)i*4) = make_uint2(h0, h1);
    *(uint2*)(g_z_lo + (size_t)i*4) = make_uint2(l0, l1);
}

// final BN2 apply: y1 -> out
__global__ void k_bn_out(float4* __restrict__ out){
    int i = blockIdx.x*256 + threadIdx.x;
    float4 v = ((const float4*)g_y1)[i];
    int c = (i & 31) << 2;
    v.x = fmaf(v.x, g_scale2[c+0], g_shift2[c+0]);
    v.y = fmaf(v.y, g_scale2[c+1], g_shift2[c+1]);
    v.z = fmaf(v.z, g_scale2[c+2], g_shift2[c+2]);
    v.w = fmaf(v.w, g_scale2[c+3], g_shift2[c+3]);
    out[i] = v;
}

// ---------------- launch ----------------
extern "C" void kernel_launch(void* const* d_in, const int* in_sizes, int n_in,
                              void* d_out, int out_size) {
    const float* x    = (const float*)d_in[0];
    const int*   ei   = (const int*)  d_in[1];
    const float* Wv   = (const float*)d_in[4];
    const float* Wout = (const float*)d_in[5];
    const float* bn1w = (const float*)d_in[6];
    const float* bn1b = (const float*)d_in[7];
    const float* W1   = (const float*)d_in[8];
    const float* b1   = (const float*)d_in[9];
    const float* W2   = (const float*)d_in[10];
    const float* b2   = (const float*)d_in[11];
    const float* bn2w = (const float*)d_in[12];
    const float* bn2b = (const float*)d_in[13];
    float* out = (float*)d_out;
    int E = in_sizes[1] / 2;

    k_prep_wv<<<192, 256>>>(Wv);
    k_prep_split<<<192, 256>>>(Wout, 3*DCH*DCH, 0);
    k_prep_split<<<768, 256>>>(W1,   3*DCH*FFH, 1);
    k_prep_split<<<768, 256>>>(W2,   3*FFH*DCH, 2);
    k_zero_mask<<<79, 256>>>();
    k_scatter_mask<<<(E + 255)/256, 256>>>(ei, E);

    for (int l = 0; l < 3; l++){
        const float* ext = (l == 0) ? x : nullptr;
        k_gemm_v  <<<157, 256>>>(ext, l);
        k_gemm_gat<<<157, 256>>>(l, ext);
        k_finalize<<<1, 128>>>(157, bn1w + l*128, bn1b + l*128, 1);
        k_bnsplit <<<2500, 256>>>();
        dim3 gf(157, 4);
        k_gemm_ff1<<<gf, 256>>>(l, b1 + l*512);
        k_gemm_ff2<<<157, 256>>>(l, b2 + l*128);
        k_finalize<<<1, 128>>>(157, bn2w + l*128, bn2b + l*128, 2);
    }
    k_bn_out<<<2500, 256>>>((float4*)out);
}

// round 10
// speedup vs baseline: 1.9279x; 1.0717x over previous
#include <cuda_runtime.h>
#include <cuda_bf16.h>

#define MROWS 20000
#define DCH   128
#define FFH   512
#define BM    128
#define BK    32
#define ASTR  40      // halves per A row (32 data + 8 pad)
#define BSTR  136     // halves per B row (128 data + 8 pad)

// byte layout of one pipeline stage in dynamic smem
#define A_PLANE   10240               // 128*ASTR*2
#define B_PLANE   8704                // 32*BSTR*2
#define OFF_AL    (A_PLANE)           // 10240
#define OFF_BH    (2*A_PLANE)         // 20480
#define OFF_BL    (2*A_PLANE+B_PLANE) // 29184
#define STAGE_B   (2*A_PLANE+2*B_PLANE) // 37888
#define SMEM_TOT  (2*STAGE_B)         // 75776

// ---------------- scratch ----------------
__device__ __nv_bfloat16 g_wv_hi[3*DCH*DCH], g_wv_lo[3*DCH*DCH];
__device__ __nv_bfloat16 g_wo_hi[3*DCH*DCH], g_wo_lo[3*DCH*DCH];
__device__ __nv_bfloat16 g_w1_hi[3*DCH*FFH], g_w1_lo[3*DCH*FFH];
__device__ __nv_bfloat16 g_w2_hi[3*FFH*DCH], g_w2_lo[3*FFH*DCH];
__device__ __nv_bfloat16 g_h_hi[MROWS*DCH],  g_h_lo[MROWS*DCH];   // layer input (BN'd), split
__device__ __nv_bfloat16 g_P_hi[MROWS*DCH],  g_P_lo[MROWS*DCH];   // permuted V
__device__ __nv_bfloat16 g_z_hi[MROWS*DCH],  g_z_lo[MROWS*DCH];   // BN1(y0), split
__device__ __nv_bfloat16 g_f_hi[MROWS*FFH],  g_f_lo[MROWS*FFH];   // relu(ff1), split
__device__ float g_y0[MROWS*DCH];     // pre-BN1 fp32
__device__ float g_y1[MROWS*DCH];     // pre-BN2 fp32
__device__ float g_part [157*DCH], g_part2[157*DCH];
__device__ float g_scale1[DCH], g_shift1[DCH], g_scale2[DCH], g_shift2[DCH];
__device__ unsigned char g_mask[MROWS];

// ---------------- helpers ----------------
__device__ __forceinline__ unsigned sptr(const void* p){
    return (unsigned)__cvta_generic_to_shared(p);
}
__device__ __forceinline__ void split2(float a, float b, unsigned& hi, unsigned& lo){
    __nv_bfloat16 ha = __float2bfloat16(a), hb = __float2bfloat16(b);
    float ra = a - __bfloat162float(ha);
    float rb = b - __bfloat162float(hb);
    __nv_bfloat162 H; H.x = ha; H.y = hb;
    __nv_bfloat162 L = __floats2bfloat162_rn(ra, rb);
    hi = *reinterpret_cast<unsigned*>(&H);
    lo = *reinterpret_cast<unsigned*>(&L);
}
__device__ __forceinline__ void ldsm4(unsigned r[4], unsigned a){
    asm volatile("ldmatrix.sync.aligned.m8n8.x4.shared.b16 {%0,%1,%2,%3}, [%4];"
        : "=r"(r[0]), "=r"(r[1]), "=r"(r[2]), "=r"(r[3]) : "r"(a));
}
__device__ __forceinline__ void ldsm4t(unsigned r[4], unsigned a){
    asm volatile("ldmatrix.sync.aligned.m8n8.x4.trans.shared.b16 {%0,%1,%2,%3}, [%4];"
        : "=r"(r[0]), "=r"(r[1]), "=r"(r[2]), "=r"(r[3]) : "r"(a));
}
__device__ __forceinline__ void mma_b(float c[4], const unsigned a[4], unsigned b0, unsigned b1){
    asm volatile("mma.sync.aligned.m16n8k16.row.col.f32.bf16.bf16.f32 "
        "{%0,%1,%2,%3}, {%4,%5,%6,%7}, {%8,%9}, {%0,%1,%2,%3};"
        : "+f"(c[0]), "+f"(c[1]), "+f"(c[2]), "+f"(c[3])
        : "r"(a[0]), "r"(a[1]), "r"(a[2]), "r"(a[3]), "r"(b0), "r"(b1));
}
__device__ __forceinline__ void cpa(unsigned d, const void* s, int srcsize){
    asm volatile("cp.async.cg.shared.global [%0], [%1], 16, %2;"
        :: "r"(d), "l"(s), "r"(srcsize));
}

// ---------------- compute: one 128x128x32 stage, 3-pass split ----------------
__device__ __forceinline__ void compute_stage(unsigned base, float acc[2][8][4]){
    int lane = threadIdx.x & 31;
    int warp = threadIdx.x >> 5;
    int wm = warp >> 1, wn = warp & 1;
    unsigned saH = base, saL = base + OFF_AL, sbH = base + OFF_BH, sbL = base + OFF_BL;
    #pragma unroll
    for (int ks = 0; ks < 2; ks++){
        unsigned aH[2][4], aL[2][4];
        #pragma unroll
        for (int mt = 0; mt < 2; mt++){
            unsigned off = (unsigned)((wm*32 + mt*16 + (lane & 15))*(ASTR*2)
                                      + ks*32 + ((lane >> 4) << 4));
            ldsm4(aH[mt], saH + off);
            ldsm4(aL[mt], saL + off);
        }
        #pragma unroll
        for (int p = 0; p < 4; p++){
            int kk = ks*16 + (lane & 15);
            int n  = wn*64 + p*16 + ((lane & 16) ? 8 : 0);
            unsigned boff = (unsigned)(kk*(BSTR*2) + n*2);
            unsigned t[4], u[4];
            ldsm4t(t, sbH + boff);
            ldsm4t(u, sbL + boff);
            #pragma unroll
            for (int mt = 0; mt < 2; mt++){
                mma_b(acc[mt][2*p],   aH[mt], t[0], t[1]);
                mma_b(acc[mt][2*p+1], aH[mt], t[2], t[3]);
                mma_b(acc[mt][2*p],   aL[mt], t[0], t[1]);
                mma_b(acc[mt][2*p+1], aL[mt], t[2], t[3]);
                mma_b(acc[mt][2*p],   aH[mt], u[0], u[1]);
                mma_b(acc[mt][2*p+1], aH[mt], u[2], u[3]);
            }
        }
    }
}

// ---------------- pipelined mainloop (double-buffered cp.async) ----------------
template<int S>
__device__ __forceinline__ void gemm_main(
    char* smem,
    const __nv_bfloat16* __restrict__ Ah, const __nv_bfloat16* __restrict__ Al,
    int lda, int row0,
    const __nv_bfloat16* __restrict__ Bh, const __nv_bfloat16* __restrict__ Bl,
    int ldb, int col0,
    float acc[2][8][4])
{
    unsigned base0 = sptr(smem);
    int tid = threadIdx.x;

    auto load = [&](int s, unsigned b){
        int k0 = s*BK;
        #pragma unroll
        for (int i = 0; i < 2; i++){
            int j = tid + i*256;
            int r = j >> 2, c8 = (j & 3) << 3;
            int gr = row0 + r;
            int sz = (gr < MROWS) ? 16 : 0;
            int grc = (gr < MROWS) ? gr : (MROWS - 1);
            size_t go = (size_t)grc*lda + k0 + c8;
            unsigned so = b + (unsigned)(r*(ASTR*2) + c8*2);
            cpa(so,          Ah + go, sz);
            cpa(so + OFF_AL, Al + go, sz);
        }
        #pragma unroll
        for (int i = 0; i < 2; i++){
            int j = tid + i*256;
            int r = j >> 4, c8 = (j & 15) << 3;
            size_t go = (size_t)(k0 + r)*ldb + col0 + c8;
            unsigned so = b + OFF_BH + (unsigned)(r*(BSTR*2) + c8*2);
            cpa(so,                     Bh + go, 16);
            cpa(so + (OFF_BL - OFF_BH), Bl + go, 16);
        }
        asm volatile("cp.async.commit_group;" ::: "memory");
    };

    load(0, base0);
    for (int s = 0; s < S; s++){
        unsigned cur = base0 + (unsigned)((s & 1) * STAGE_B);
        if (s + 1 < S){
            load(s + 1, base0 + (unsigned)(((s + 1) & 1) * STAGE_B));
            asm volatile("cp.async.wait_group 1;" ::: "memory");
        } else {
            asm volatile("cp.async.wait_group 0;" ::: "memory");
        }
        __syncthreads();
        compute_stage(cur, acc);
        __syncthreads();
    }
}

// deterministic per-block column sum/sumsq
__device__ __forceinline__ void block_stats(float acc[2][8][4], float* redS, float* redQ, int slot)
{
    int tid = threadIdx.x;
    int lane = tid & 31, warp = tid >> 5, wm = warp >> 1, wn = warp & 1;
    #pragma unroll
    for (int nt = 0; nt < 8; nt++){
        float se=0.f, so=0.f, qe=0.f, qo=0.f;
        #pragma unroll
        for (int mt = 0; mt < 2; mt++){
            float a0=acc[mt][nt][0], a1=acc[mt][nt][1], a2=acc[mt][nt][2], a3=acc[mt][nt][3];
            se += a0 + a2; so += a1 + a3;
            qe += a0*a0 + a2*a2; qo += a1*a1 + a3*a3;
        }
        #pragma unroll
        for (int off = 16; off >= 4; off >>= 1){
            se += __shfl_down_sync(0xffffffffu, se, off);
            so += __shfl_down_sync(0xffffffffu, so, off);
            qe += __shfl_down_sync(0xffffffffu, qe, off);
            qo += __shfl_down_sync(0xffffffffu, qo, off);
        }
        if (lane < 4){
            int c = wn*64 + nt*8 + lane*2;
            redS[wm*128 + c] = se; redS[wm*128 + c + 1] = so;
            redQ[wm*128 + c] = qe; redQ[wm*128 + c + 1] = qo;
        }
    }
    __syncthreads();
    if (tid < 128){
        float s = redS[tid] + redS[128+tid] + redS[256+tid] + redS[384+tid];
        float q = redQ[tid] + redQ[128+tid] + redQ[256+tid] + redQ[384+tid];
        g_part [slot*128 + tid] = s;
        g_part2[slot*128 + tid] = q;
    }
}

#define ACC_INIT float acc[2][8][4]; \
    _Pragma("unroll") for (int _i=0;_i<2;_i++) \
    _Pragma("unroll") for (int _j=0;_j<8;_j++) \
    _Pragma("unroll") for (int _k=0;_k<4;_k++) acc[_i][_j][_k]=0.f;

#define EPI_COORDS int tid = threadIdx.x; int lane = tid & 31; int warp = tid >> 5; \
    int wm = warp >> 1, wn = warp & 1; \
    int rb = row0 + wm*32 + (lane>>4); \
    int cb = wn*64 + ((lane&3)<<1); (void)cb; (void)tid;

// NOTE: rb uses (lane>>2) — corrected in macro below (kept single definition)
#undef EPI_COORDS
#define EPI_COORDS int tid = threadIdx.x; int lane = tid & 31; int warp = tid >> 5; \
    int wm = warp >> 1, wn = warp & 1; \
    int rb = row0 + wm*32 + (lane>>2); \
    int cb = wn*64 + ((lane&3)<<1); (void)cb; (void)tid;

// ---------------- GEMM 1: P(permuted,split) = h @ Wv ----------------
__global__ __launch_bounds__(256, 2) void k_gemm_v(int l)
{
    extern __shared__ char smem[];
    ACC_INIT
    int row0 = blockIdx.x*BM;
    gemm_main<4>(smem, g_h_hi, g_h_lo, DCH, row0,
                 g_wv_hi + l*DCH*DCH, g_wv_lo + l*DCH*DCH, DCH, 0, acc);
    EPI_COORDS
    #pragma unroll
    for (int mt = 0; mt < 2; mt++)
    #pragma unroll
    for (int hf = 0; hf < 2; hf++){
        int r = rb + mt*16 + hf*8;
        if (r < MROWS){
            int m = r >> 3, rr = r & 7;
            #pragma unroll
            for (int nt = 0; nt < 8; nt++){
                int c = cb + nt*8;
                int g = c >> 4;
                size_t off = (size_t)(g*2500 + m)*DCH + (rr << 4) + (c & 15);
                unsigned hi, lo;
                split2(acc[mt][nt][hf*2], acc[mt][nt][hf*2+1], hi, lo);
                *(unsigned*)(g_P_hi + off) = hi;
                *(unsigned*)(g_P_lo + off) = lo;
            }
        }
    }
}

// ---------------- GEMM 2: y0 = h + mask*(P @ Wout), BN1 partial stats ----------------
__global__ __launch_bounds__(256, 2) void k_gemm_gat(int l)
{
    extern __shared__ char smem[];
    ACC_INIT
    int row0 = blockIdx.x*BM;
    gemm_main<4>(smem, g_P_hi, g_P_lo, DCH, row0,
                 g_wo_hi + l*DCH*DCH, g_wo_lo + l*DCH*DCH, DCH, 0, acc);
    EPI_COORDS
    #pragma unroll
    for (int mt = 0; mt < 2; mt++)
    #pragma unroll
    for (int hf = 0; hf < 2; hf++){
        int r = rb + mt*16 + hf*8;
        if (r < MROWS){
            float mk = g_mask[r] ? 1.f : 0.f;
            #pragma unroll
            for (int nt = 0; nt < 8; nt++){
                int c = cb + nt*8;
                size_t off = (size_t)r*DCH + c;
                unsigned ph = *(const unsigned*)(g_h_hi + off);
                unsigned pl = *(const unsigned*)(g_h_lo + off);
                __nv_bfloat162 Hh = *reinterpret_cast<__nv_bfloat162*>(&ph);
                __nv_bfloat162 Hl = *reinterpret_cast<__nv_bfloat162*>(&pl);
                float h0 = __bfloat162float(Hh.x) + __bfloat162float(Hl.x);
                float h1 = __bfloat162float(Hh.y) + __bfloat162float(Hl.y);
                float v0 = fmaf(mk, acc[mt][nt][hf*2+0], h0);
                float v1 = fmaf(mk, acc[mt][nt][hf*2+1], h1);
                *(float2*)(g_y0 + off) = make_float2(v0, v1);
                acc[mt][nt][hf*2+0] = v0; acc[mt][nt][hf*2+1] = v1;
            }
        } else {
            #pragma unroll
            for (int nt = 0; nt < 8; nt++){ acc[mt][nt][hf*2+0]=0.f; acc[mt][nt][hf*2+1]=0.f; }
        }
    }
    block_stats(acc, (float*)smem, (float*)(smem + 2048), blockIdx.x);
}

// ---------------- GEMM 3: f = relu(z @ W1 + b1), split output ----------------
__global__ __launch_bounds__(256, 2) void k_gemm_ff1(int l, const float* __restrict__ bias)
{
    extern __shared__ char smem[];
    ACC_INIT
    int row0 = blockIdx.x*BM;
    int col0 = blockIdx.y*128;
    gemm_main<4>(smem, g_z_hi, g_z_lo, DCH, row0,
                 g_w1_hi + l*DCH*FFH, g_w1_lo + l*DCH*FFH, FFH, col0, acc);
    EPI_COORDS
    #pragma unroll
    for (int mt = 0; mt < 2; mt++)
    #pragma unroll
    for (int hf = 0; hf < 2; hf++){
        int r = rb + mt*16 + hf*8;
        if (r < MROWS){
            #pragma unroll
            for (int nt = 0; nt < 8; nt++){
                int c = cb + nt*8;
                float v0 = fmaxf(acc[mt][nt][hf*2+0] + bias[col0+c],   0.f);
                float v1 = fmaxf(acc[mt][nt][hf*2+1] + bias[col0+c+1], 0.f);
                unsigned hi, lo;
                split2(v0, v1, hi, lo);
                size_t off = (size_t)r*FFH + col0 + c;
                *(unsigned*)(g_f_hi + off) = hi;
                *(unsigned*)(g_f_lo + off) = lo;
            }
        }
    }
}

// ---------------- GEMM 4: y1 = z + f @ W2 + b2, BN2 partial stats ----------------
__global__ __launch_bounds__(256, 2) void k_gemm_ff2(int l, const float* __restrict__ bias)
{
    extern __shared__ char smem[];
    ACC_INIT
    int row0 = blockIdx.x*BM;
    gemm_main<16>(smem, g_f_hi, g_f_lo, FFH, row0,
                  g_w2_hi + l*FFH*DCH, g_w2_lo + l*FFH*DCH, DCH, 0, acc);
    EPI_COORDS
    #pragma unroll
    for (int mt = 0; mt < 2; mt++)
    #pragma unroll
    for (int hf = 0; hf < 2; hf++){
        int r = rb + mt*16 + hf*8;
        if (r < MROWS){
            #pragma unroll
            for (int nt = 0; nt < 8; nt++){
                int c = cb + nt*8;
                size_t off = (size_t)r*DCH + c;
                unsigned ph = *(const unsigned*)(g_z_hi + off);
                unsigned pl = *(const unsigned*)(g_z_lo + off);
                __nv_bfloat162 Zh = *reinterpret_cast<__nv_bfloat162*>(&ph);
                __nv_bfloat162 Zl = *reinterpret_cast<__nv_bfloat162*>(&pl);
                float z0 = __bfloat162float(Zh.x) + __bfloat162float(Zl.x);
                float z1 = __bfloat162float(Zh.y) + __bfloat162float(Zl.y);
                float v0 = z0 + acc[mt][nt][hf*2+0] + bias[c];
                float v1 = z1 + acc[mt][nt][hf*2+1] + bias[c+1];
                *(float2*)(g_y1 + off) = make_float2(v0, v1);
                acc[mt][nt][hf*2+0] = v0; acc[mt][nt][hf*2+1] = v1;
            }
        } else {
            #pragma unroll
            for (int nt = 0; nt < 8; nt++){ acc[mt][nt][hf*2+0]=0.f; acc[mt][nt][hf*2+1]=0.f; }
        }
    }
    block_stats(acc, (float*)smem, (float*)(smem + 2048), blockIdx.x);
}

// ---------------- small kernels ----------------
__global__ void k_prep_all(const float* __restrict__ Wv, const float* __restrict__ Wo,
                           const float* __restrict__ W1, const float* __restrict__ W2){
    int idx = blockIdx.x*256 + threadIdx.x;
    if (idx < 49152){
        int l = idx / (DCH*DCH);
        int rmd = idx % (DCH*DCH);
        int d = rmd / DCH, col = rmd % DCH;
        int g = col >> 4, k = col & 15;
        float v = Wv[((l*8 + g)*DCH + d)*16 + k];
        __nv_bfloat16 h = __float2bfloat16(v);
        g_wv_hi[idx] = h;
        g_wv_lo[idx] = __float2bfloat16(v - __bfloat162float(h));
    } else if (idx < 98304){
        int i = idx - 49152;
        float v = Wo[i];
        __nv_bfloat16 h = __float2bfloat16(v);
        g_wo_hi[i] = h; g_wo_lo[i] = __float2bfloat16(v - __bfloat162float(h));
    } else if (idx < 294912){
        int i = idx - 98304;
        float v = W1[i];
        __nv_bfloat16 h = __float2bfloat16(v);
        g_w1_hi[i] = h; g_w1_lo[i] = __float2bfloat16(v - __bfloat162float(h));
    } else if (idx < 491520){
        int i = idx - 294912;
        float v = W2[i];
        __nv_bfloat16 h = __float2bfloat16(v);
        g_w2_hi[i] = h; g_w2_lo[i] = __float2bfloat16(v - __bfloat162float(h));
    } else if (idx < 511520){
        g_mask[idx - 491520] = 0;
    }
}

__global__ void k_scatter_mask(const int* __restrict__ ei, int E){
    int e = blockIdx.x*256 + threadIdx.x;
    if (e < E) g_mask[ei[E + e]] = 1;   // dst row
}

// x -> h split (layer 0 input)
__global__ void k_split_x(const float4* __restrict__ x){
    int i = blockIdx.x*256 + threadIdx.x;     // 640000 float4 exactly
    float4 v = x[i];
    unsigned h0,l0,h1,l1;
    split2(v.x, v.y, h0, l0);
    split2(v.z, v.w, h1, l1);
    *(uint2*)(g_h_hi + (size_t)i*4) = make_uint2(h0, h1);
    *(uint2*)(g_h_lo + (size_t)i*4) = make_uint2(l0, l1);
}

__global__ void k_finalize(int nslots, const float* __restrict__ w,
                           const float* __restrict__ b, int which){
    int c = threadIdx.x;   // 128
    float s = 0.f, q = 0.f;
    for (int i = 0; i < nslots; i++){ s += g_part[i*128 + c]; q += g_part2[i*128 + c]; }
    float inv = 1.f / (float)MROWS;
    float mu = s * inv;
    float var = q * inv - mu*mu;
    float sc = rsqrtf(var + 1e-5f) * w[c];
    if (which == 1){ g_scale1[c] = sc; g_shift1[c] = b[c] - mu*sc; }
    else           { g_scale2[c] = sc; g_shift2[c] = b[c] - mu*sc; }
}

// BN1 apply + split: y0 -> z
__global__ void k_bnsplit(){
    int i = blockIdx.x*256 + threadIdx.x;     // 640000 float4
    float4 v = ((const float4*)g_y0)[i];
    int c = (i & 31) << 2;
    v.x = fmaf(v.x, g_scale1[c+0], g_shift1[c+0]);
    v.y = fmaf(v.y, g_scale1[c+1], g_shift1[c+1]);
    v.z = fmaf(v.z, g_scale1[c+2], g_shift1[c+2]);
    v.w = fmaf(v.w, g_scale1[c+3], g_shift1[c+3]);
    unsigned h0,l0,h1,l1;
    split2(v.x, v.y, h0, l0);
    split2(v.z, v.w, h1, l1);
    *(uint2*)(g_z_hi + (size_t)i*4) = make_uint2(h0, h1);
    *(uint2*)(g_z_lo + (size_t)i*4) = make_uint2(l0, l1);
}

// BN2 apply: y1 -> h split (next layer) or fp32 out (last layer)
__global__ void k_bn2(int last, float4* __restrict__ out){
    int i = blockIdx.x*256 + threadIdx.x;
    float4 v = ((const float4*)g_y1)[i];
    int c = (i & 31) << 2;
    v.x = fmaf(v.x, g_scale2[c+0], g_shift2[c+0]);
    v.y = fmaf(v.y, g_scale2[c+1], g_shift2[c+1]);
    v.z = fmaf(v.z, g_scale2[c+2], g_shift2[c+2]);
    v.w = fmaf(v.w, g_scale2[c+3], g_shift2[c+3]);
    if (last){
        out[i] = v;
    } else {
        unsigned h0,l0,h1,l1;
        split2(v.x, v.y, h0, l0);
        split2(v.z, v.w, h1, l1);
        *(uint2*)(g_h_hi + (size_t)i*4) = make_uint2(h0, h1);
        *(uint2*)(g_h_lo + (size_t)i*4) = make_uint2(l0, l1);
    }
}

// ---------------- launch ----------------
extern "C" void kernel_launch(void* const* d_in, const int* in_sizes, int n_in,
                              void* d_out, int out_size) {
    const float* x    = (const float*)d_in[0];
    const int*   ei   = (const int*)  d_in[1];
    const float* Wv   = (const float*)d_in[4];
    const float* Wout = (const float*)d_in[5];
    const float* bn1w = (const float*)d_in[6];
    const float* bn1b = (const float*)d_in[7];
    const float* W1   = (const float*)d_in[8];
    const float* b1   = (const float*)d_in[9];
    const float* W2   = (const float*)d_in[10];
    const float* b2   = (const float*)d_in[11];
    const float* bn2w = (const float*)d_in[12];
    const float* bn2b = (const float*)d_in[13];
    float* out = (float*)d_out;
    int E = in_sizes[1] / 2;

    cudaFuncSetAttribute(k_gemm_v,   cudaFuncAttributeMaxDynamicSharedMemorySize, SMEM_TOT);
    cudaFuncSetAttribute(k_gemm_gat, cudaFuncAttributeMaxDynamicSharedMemorySize, SMEM_TOT);
    cudaFuncSetAttribute(k_gemm_ff1, cudaFuncAttributeMaxDynamicSharedMemorySize, SMEM_TOT);
    cudaFuncSetAttribute(k_gemm_ff2, cudaFuncAttributeMaxDynamicSharedMemorySize, SMEM_TOT);

    k_prep_all<<<1999, 256>>>(Wv, Wout, W1, W2);
    k_scatter_mask<<<(E + 255)/256, 256>>>(ei, E);
    k_split_x<<<2500, 256>>>((const float4*)x);

    for (int l = 0; l < 3; l++){
        k_gemm_v  <<<157, 256, SMEM_TOT>>>(l);
        k_gemm_gat<<<157, 256, SMEM_TOT>>>(l);
        k_finalize<<<1, 128>>>(157, bn1w + l*128, bn1b + l*128, 1);
        k_bnsplit <<<2500, 256>>>();
        dim3 gf(157, 4);
        k_gemm_ff1<<<gf, 256, SMEM_TOT>>>(l, b1 + l*512);
        k_gemm_ff2<<<157, 256, SMEM_TOT>>>(l, b2 + l*128);
        k_finalize<<<1, 128>>>(157, bn2w + l*128, bn2b + l*128, 2);
        k_bn2     <<<2500, 256>>>((l == 2) ? 1 : 0, (float4*)out);
    }
}